// round 1
// baseline (speedup 1.0000x reference)
#include <cuda_runtime.h>

#define B     64
#define TAPE  262144
#define OUT   65536
#define FANIN 16

// Scratch (allocation-free rule: __device__ globals)
__device__ float g_tape_T[(size_t)TAPE * B];  // 64 MB: tape transposed to [TAPE, B]
__device__ float g_x_T[(size_t)OUT * B];      // 16 MB: results [OUT, B]
__device__ int   g_is64;                      // 1 if index arrays are int64, 0 if int32

// ---------------------------------------------------------------------------
// Dtype probe: input_indices values are in [0, 262144). If stored as int64,
// every odd 32-bit word is 0. If int32 (JAX x64 disabled), odd words are
// random indices (P[all 64 zero] ~ (1/262144)^64 ~ 0).
// ---------------------------------------------------------------------------
__global__ void detect_kernel(const int* __restrict__ idx_words) {
    if (threadIdx.x == 0) {
        int is64 = 1;
        #pragma unroll 1
        for (int i = 0; i < 64; i++) {
            if (idx_words[2 * i + 1] != 0) { is64 = 0; break; }
        }
        g_is64 = is64;
    }
}

// ---------------------------------------------------------------------------
// Transpose tape [B, TAPE] -> g_tape_T [TAPE, B]. Tile 64 (tape) x 64 (batch).
// Block (64, 8). Fully coalesced both sides, smem padded against conflicts.
// ---------------------------------------------------------------------------
__global__ void transpose_kernel(const float* __restrict__ tape) {
    __shared__ float s[64][65];
    const int t0 = blockIdx.x * 64;
    const int tx = threadIdx.x;   // 0..63
    const int ty = threadIdx.y;   // 0..7

    #pragma unroll
    for (int i = 0; i < 64; i += 8) {
        // s[col][b]
        s[tx][ty + i] = tape[(size_t)(ty + i) * TAPE + t0 + tx];
    }
    __syncthreads();
    #pragma unroll
    for (int i = 0; i < 64; i += 8) {
        g_tape_T[(size_t)(t0 + ty + i) * B + tx] = s[ty + i][tx];
    }
}

// ---------------------------------------------------------------------------
// Core: one warp per output node. Lane l accumulates batches (2l, 2l+1) in a
// float2. Each of the 16 fanin indices fetches 256 contiguous, 256B-aligned
// bytes from g_tape_T (perfectly coalesced LDG.64 across the warp).
// ---------------------------------------------------------------------------
__global__ void gather_mm_kernel(const float* __restrict__ weights,
                                 const float* __restrict__ bias,
                                 const void*  __restrict__ input_indices,
                                 const void*  __restrict__ act_ids) {
    const int gwarp = (blockIdx.x * blockDim.x + threadIdx.x) >> 5;
    const int lane  = threadIdx.x & 31;
    if (gwarp >= OUT) return;
    const int o = gwarp;
    const int is64 = g_is64;

    const long long* i64 = (const long long*)input_indices;
    const int*       i32 = (const int*)input_indices;

    const float bv = __ldg(bias + o);
    float2 acc = make_float2(bv, bv);

    #pragma unroll
    for (int f = 0; f < FANIN; f++) {
        const int idx = is64 ? (int)i64[(size_t)o * FANIN + f]
                             : i32[(size_t)o * FANIN + f];
        const float w = __ldg(weights + (size_t)o * FANIN + f);
        const float2 v = ((const float2*)(g_tape_T + (size_t)idx * B))[lane];
        acc.x = fmaf(w, v.x, acc.x);
        acc.y = fmaf(w, v.y, acc.y);
    }

    const int a = is64 ? (int)((const long long*)act_ids)[o]
                       : ((const int*)act_ids)[o];
    if (a == 0) {
        acc.x = fmaxf(acc.x, 0.f);
        acc.y = fmaxf(acc.y, 0.f);
    } else if (a == 1) {
        acc.x = 1.f / (1.f + __expf(-acc.x));
        acc.y = 1.f / (1.f + __expf(-acc.y));
    } else {
        acc.x = tanhf(acc.x);
        acc.y = tanhf(acc.y);
    }

    ((float2*)(g_x_T + (size_t)o * B))[lane] = acc;
}

// ---------------------------------------------------------------------------
// Scatter x_T [OUT, B] into out [B, TAPE] at output_indices, via a 32x32
// smem transpose tile so both the x_T reads and the out writes coalesce
// (output_indices is arange in practice, honored generally anyway).
// ---------------------------------------------------------------------------
__global__ void scatter_kernel(float* __restrict__ out,
                               const void* __restrict__ output_indices) {
    __shared__ float s[32][33];
    const int o0 = blockIdx.x * 32;
    const int b0 = blockIdx.y * 32;
    const int tx = threadIdx.x;   // 0..31
    const int ty = threadIdx.y;   // 0..7

    #pragma unroll
    for (int i = 0; i < 32; i += 8)
        s[ty + i][tx] = g_x_T[(size_t)(o0 + ty + i) * B + b0 + tx];
    __syncthreads();

    const int is64 = g_is64;
    const int oi = is64 ? (int)((const long long*)output_indices)[o0 + tx]
                        : ((const int*)output_indices)[o0 + tx];

    #pragma unroll
    for (int i = 0; i < 32; i += 8)
        out[(size_t)(b0 + ty + i) * TAPE + oi] = s[tx][ty + i];
}

// ---------------------------------------------------------------------------
extern "C" void kernel_launch(void* const* d_in, const int* in_sizes, int n_in,
                              void* d_out, int out_size) {
    const float* tape           = (const float*)d_in[0];
    const float* weights        = (const float*)d_in[1];
    const float* bias           = (const float*)d_in[2];
    const void*  input_indices  = d_in[3];
    const void*  output_indices = d_in[4];
    const void*  act_ids        = d_in[5];
    float* out = (float*)d_out;

    // 1. Probe index dtype (int64 vs silently-demoted int32)
    detect_kernel<<<1, 32>>>((const int*)input_indices);

    // 2. Transpose tape -> [TAPE, B] so gathers are coalesced across batch
    transpose_kernel<<<TAPE / 64, dim3(64, 8)>>>(tape);

    // 3. out = tape (reference copies the full tape, then scatters)
    cudaMemcpyAsync(out, tape, (size_t)B * TAPE * sizeof(float),
                    cudaMemcpyDeviceToDevice);

    // 4. Gather + weighted sum + activation -> x_T [OUT, B]
    gather_mm_kernel<<<OUT / 8, 256>>>(weights, bias, input_indices, act_ids);

    // 5. Transpose-scatter x_T into out
    scatter_kernel<<<dim3(OUT / 32, B / 32), dim3(32, 8)>>>(out, output_indices);
}

// round 2
// speedup vs baseline: 1.3605x; 1.3605x over previous
#include <cuda_runtime.h>

#define B     64
#define TAPE  262144
#define OUT   65536
#define FANIN 16

// Scratch (allocation-free rule: __device__ globals)
__device__ float g_tape_T[(size_t)TAPE * B];  // 64 MB: tape transposed to [TAPE, B]
__device__ int   g_is64;                      // 1 if index arrays are int64, 0 if int32

// ---------------------------------------------------------------------------
// Dtype probe: input_indices values are in [0, 262144). If stored as int64,
// every odd 32-bit word is 0. If int32 (JAX x64 disabled), odd words are
// random indices (P[all 64 zero] ~ (1/262144)^64 ~ 0).
// ---------------------------------------------------------------------------
__global__ void detect_kernel(const int* __restrict__ idx_words) {
    if (threadIdx.x == 0) {
        int is64 = 1;
        #pragma unroll 1
        for (int i = 0; i < 64; i++) {
            if (idx_words[2 * i + 1] != 0) { is64 = 0; break; }
        }
        g_is64 = is64;
    }
}

// ---------------------------------------------------------------------------
// Fused: tape [B, TAPE] -> (a) g_tape_T [TAPE, B] (transposed),
//                          (b) out (straight copy, same layout).
// Reads tape exactly once from DRAM. Tile 64 (tape) x 64 (batch), block (64,8).
// ---------------------------------------------------------------------------
__global__ void transpose_copy_kernel(const float* __restrict__ tape,
                                      float* __restrict__ out) {
    __shared__ float s[64][65];
    const int t0 = blockIdx.x * 64;
    const int tx = threadIdx.x;   // 0..63  (tape position within tile)
    const int ty = threadIdx.y;   // 0..7   (batch stride)

    #pragma unroll
    for (int i = 0; i < 64; i += 8) {
        const size_t off = (size_t)(ty + i) * TAPE + t0 + tx;
        const float v = tape[off];
        out[off] = v;                 // straight copy (coalesced)
        s[tx][ty + i] = v;            // stage for transpose
    }
    __syncthreads();
    #pragma unroll
    for (int i = 0; i < 64; i += 8) {
        g_tape_T[(size_t)(t0 + ty + i) * B + tx] = s[ty + i][tx];
    }
}

// ---------------------------------------------------------------------------
// Fused gather + weighted-sum + activation + scatter.
// Block = 512 threads = 16 warps = 16 output nodes. Warp w owns output o0+w;
// lane l accumulates batches (2l, 2l+1) as a float2 from coalesced 256B rows
// of g_tape_T. Indices/weights/bias/act/out-indices are loaded cooperatively
// into smem once per block. Results go through a padded smem tile so the
// final writes to `out` are contiguous runs (64B per 16 threads) when
// output_indices is arange (correct for arbitrary indices too).
// ---------------------------------------------------------------------------
__global__ void __launch_bounds__(512)
gather_scatter_kernel(const float* __restrict__ weights,
                      const float* __restrict__ bias,
                      const void*  __restrict__ input_indices,
                      const void*  __restrict__ output_indices,
                      const void*  __restrict__ act_ids,
                      float* __restrict__ out) {
    __shared__ int   s_idx[256];     // 16 outputs x 16 fanin
    __shared__ float s_w[256];
    __shared__ float s_bias[16];
    __shared__ int   s_act[16];
    __shared__ int   s_oi[16];
    __shared__ float sx[16][66];     // [output][batch], padded: bank-conflict-free

    const int t    = threadIdx.x;        // 0..511
    const int warp = t >> 5;             // 0..15
    const int lane = t & 31;
    const int o0   = blockIdx.x * 16;
    const int is64 = g_is64;

    // Cooperative metadata loads
    if (t < 256) {
        if (is64) {
            s_idx[t] = (int)((const long long*)input_indices)[(size_t)o0 * FANIN + t];
        } else {
            s_idx[t] = ((const int*)input_indices)[(size_t)o0 * FANIN + t];
        }
        s_w[t] = weights[(size_t)o0 * FANIN + t];
    } else if (t < 256 + 16) {
        const int j = t - 256;
        s_bias[j] = bias[o0 + j];
        s_act[j]  = is64 ? (int)((const long long*)act_ids)[o0 + j]
                         : ((const int*)act_ids)[o0 + j];
        s_oi[j]   = is64 ? (int)((const long long*)output_indices)[o0 + j]
                         : ((const int*)output_indices)[o0 + j];
    }
    __syncthreads();

    // Gather + dot: warp `warp` -> output o0+warp
    const float bv = s_bias[warp];
    float2 acc = make_float2(bv, bv);

    #pragma unroll
    for (int f = 0; f < FANIN; f++) {
        const int   idx = s_idx[warp * FANIN + f];
        const float w   = s_w[warp * FANIN + f];
        const float2 v  = ((const float2*)(g_tape_T + (size_t)idx * B))[lane];
        acc.x = fmaf(w, v.x, acc.x);
        acc.y = fmaf(w, v.y, acc.y);
    }

    const int a = s_act[warp];
    if (a == 0) {
        acc.x = fmaxf(acc.x, 0.f);
        acc.y = fmaxf(acc.y, 0.f);
    } else if (a == 1) {
        acc.x = 1.f / (1.f + __expf(-acc.x));
        acc.y = 1.f / (1.f + __expf(-acc.y));
    } else {
        acc.x = tanhf(acc.x);
        acc.y = tanhf(acc.y);
    }

    sx[warp][lane * 2]     = acc.x;
    sx[warp][lane * 2 + 1] = acc.y;
    __syncthreads();

    // Transposed scatter: thread t writes output j = t%16, batches t/16 and t/16+32.
    // For arange output_indices, 16 consecutive threads write 64 contiguous bytes.
    const int j  = t & 15;
    const int b0 = t >> 4;               // 0..31
    const int oi = s_oi[j];
    out[(size_t)b0 * TAPE + oi]        = sx[j][b0];
    out[(size_t)(b0 + 32) * TAPE + oi] = sx[j][b0 + 32];
}

// ---------------------------------------------------------------------------
extern "C" void kernel_launch(void* const* d_in, const int* in_sizes, int n_in,
                              void* d_out, int out_size) {
    const float* tape           = (const float*)d_in[0];
    const float* weights        = (const float*)d_in[1];
    const float* bias           = (const float*)d_in[2];
    const void*  input_indices  = d_in[3];
    const void*  output_indices = d_in[4];
    const void*  act_ids        = d_in[5];
    float* out = (float*)d_out;

    // 1. Probe index dtype (int64 vs silently-demoted int32)
    detect_kernel<<<1, 32>>>((const int*)input_indices);

    // 2. Single-pass: out = tape copy; g_tape_T = transpose(tape)
    transpose_copy_kernel<<<TAPE / 64, dim3(64, 8)>>>(tape, out);

    // 3. Fused gather + dot + activation + scatter into out
    gather_scatter_kernel<<<OUT / 16, 512>>>(weights, bias, input_indices,
                                             output_indices, act_ids, out);
}